// round 9
// baseline (speedup 1.0000x reference)
#include <cuda_runtime.h>
#include <math.h>
#include <stdint.h>

// Problem constants (fixed shapes for GCM_60490319396973)
constexpr int N_   = 40000;
constexpr int DIM_ = 256;
constexpr int H_   = 128;
constexpr int K_   = 27;
constexpr int B_   = 4;
constexpr int KH_  = K_ * H_;      // 3456
constexpr int NPART = 250;
constexpr int CHUNK = (N_ + NPART - 1) / NPART;   // 160

// ---------------- scratch (device globals: no allocation allowed) ----------
__device__ float g_convx[(N_ + 1) * H_];   // padded: row N_ is the zero row
__device__ float g_glo  [(N_ + 1) * H_];
__device__ float g_r1   [(N_ + 1) * H_];
__device__ float g_convout[N_ * H_];
__device__ float g_f1[N_ * H_];
__device__ float g_f2[N_ * H_];
__device__ float g_t [N_ * H_];
__device__ float g_part[NPART * B_ * H_];
__device__ int   g_cnt [NPART * B_];
__device__ float g_m2  [B_ * H_];
// tf32-pre-rounded operands
__device__ float g_xr  [N_ * DIM_];
__device__ float g_W1r [DIM_ * DIM_];
__device__ float g_W2r [DIM_ * DIM_];
__device__ float g_Wg3r[H_ * H_];
__device__ float g_Wr1r[KH_ * H_];
__device__ float g_Wr2r[KH_ * H_];
__device__ float g_Wg1r[KH_ * H_];
__device__ float g_Wg2r[KH_ * H_];

// ---------------- helpers ----------------------------------------------------
__device__ __forceinline__ uint32_t f2tf32(float x) {
    uint32_t y;
    asm("cvt.rna.tf32.f32 %0, %1;" : "=r"(y) : "f"(x));
    return y;
}
__device__ __forceinline__ float rnd_tf32(float x) {
    return __uint_as_float(f2tf32(x));
}
__device__ __forceinline__ void mma_tf32(float c[4], const uint32_t a[4],
                                         const uint32_t b[2]) {
    asm volatile(
        "mma.sync.aligned.m16n8k8.row.col.f32.tf32.tf32.f32 "
        "{%0,%1,%2,%3}, {%4,%5,%6,%7}, {%8,%9}, {%0,%1,%2,%3};\n"
        : "+f"(c[0]), "+f"(c[1]), "+f"(c[2]), "+f"(c[3])
        : "r"(a[0]), "r"(a[1]), "r"(a[2]), "r"(a[3]), "r"(b[0]), "r"(b[1]));
}
__device__ __forceinline__ void cp16(uint32_t dst, const void* src, bool valid) {
    asm volatile("cp.async.cg.shared.global [%0], [%1], 16, %2;"
                 :: "r"(dst), "l"(src), "r"(valid ? 16 : 0));
}
__device__ __forceinline__ void cp16g(uint32_t dst, const void* src) {
    asm volatile("cp.async.cg.shared.global [%0], [%1], 16;"
                 :: "r"(dst), "l"(src));
}
__device__ __forceinline__ void cp_commit() {
    asm volatile("cp.async.commit_group;");
}
__device__ __forceinline__ void cp_wait0() {
    asm volatile("cp.async.wait_group 0;");
}

// ---------------- tiny kernels ---------------------------------------------
__global__ void zero_pad_kernel() {
    int t = threadIdx.x;                 // 128 threads
    g_convx[N_ * H_ + t] = 0.f;
    g_glo  [N_ * H_ + t] = 0.f;
    g_r1   [N_ * H_ + t] = 0.f;
}

__global__ void round_copy_kernel(const float* __restrict__ src,
                                  float* __restrict__ dst, int n4) {
    int i = blockIdx.x * blockDim.x + threadIdx.x;
    if (i >= n4) return;
    float4 v = reinterpret_cast<const float4*>(src)[i];
    v.x = rnd_tf32(v.x); v.y = rnd_tf32(v.y);
    v.z = rnd_tf32(v.z); v.w = rnd_tf32(v.w);
    reinterpret_cast<float4*>(dst)[i] = v;
}

// ---------------- big-tile sconv (mma.sync tf32, 256x128 block) -------------
// C[m, 0:128] = epi( bias + sum_{k,c} A[nbr[m,k], c] * W[k*128+c, :] )
enum { EPI_RELU = 0, EPI_R2 = 1 };

constexpr int SBK = 32;
constexpr int SPA = SBK + 4;                 // 36
constexpr int SPB = H_ + 8;                  // 136
constexpr int SM_ROWS = 256;
constexpr int SCONV_SMEM = 2 * SM_ROWS * SPA * 4   // A double buffer  73728
                         + 2 * SBK * SPB * 4       // B double buffer  34816
                         + SM_ROWS * K_ * 4;       // snbr             27648

template <int EPI, int RND>
__global__ void __launch_bounds__(256, 1)
sconv_big_kernel(const float* __restrict__ A,   // (N_+1) x 128, rounded, zero row N_
                 const int* __restrict__ nbr,
                 const float* __restrict__ Bm,  // [3456][128], rounded
                 const float* __restrict__ bias,
                 const float* __restrict__ aux,
                 float* __restrict__ C)
{
    extern __shared__ char smem_raw[];
    float* As   = reinterpret_cast<float*>(smem_raw);        // [2][256][SPA]
    float* Bs   = As + 2 * SM_ROWS * SPA;                    // [2][32][SPB]
    int*   snbr = reinterpret_cast<int*>(Bs + 2 * SBK * SPB);// [256][27]

    const int tid  = threadIdx.x;
    const int m0   = blockIdx.x * SM_ROWS;
    const int lane = tid & 31;
    const int wid  = tid >> 5;         // 0..7
    const int wm   = wid & 3;          // warp row (4 x 64 = 256)
    const int wn   = wid >> 2;         // warp col (2 x 64 = 128)
    const int g    = lane >> 2;        // 0..7
    const int tg   = lane & 3;         // 0..3

    for (int i = tid; i < SM_ROWS * K_; i += 256) {
        int r = i / K_, k = i % K_;
        int row = m0 + r;
        snbr[i] = (row < N_) ? nbr[row * K_ + k] : N_;   // N_ -> zero row
    }
    __syncthreads();

    auto stage = [&](int t, int buf) {
        int k0 = t * SBK;
        int kidx = k0 >> 7;                 // neighbor slot
        int csub = k0 & 127;                // feature offset within row
        float* Ab = As + buf * SM_ROWS * SPA;
        float* Bb = Bs + buf * SBK * SPB;
        // A: 256 rows x 32 cols = 2048 float4
#pragma unroll
        for (int it = 0; it < 8; it++) {
            int idx = tid + it * 256;
            int r   = idx >> 3;            // 0..255
            int c4  = (idx & 7) << 2;      // 0..28
            uint32_t dst = (uint32_t)__cvta_generic_to_shared(&Ab[r * SPA + c4]);
            int src = snbr[r * K_ + kidx];
            cp16g(dst, A + (size_t)src * H_ + csub + c4);
        }
        // B: 32 rows x 128 cols = 1024 float4
#pragma unroll
        for (int it = 0; it < 4; it++) {
            int idx = tid + it * 256;
            int r   = idx >> 5;            // 0..31
            int c4  = (idx & 31) << 2;     // 0..124
            uint32_t dst = (uint32_t)__cvta_generic_to_shared(&Bb[r * SPB + c4]);
            cp16g(dst, Bm + (size_t)(k0 + r) * H_ + c4);
        }
    };

    float acc[4][8][4];
#pragma unroll
    for (int mt = 0; mt < 4; mt++)
#pragma unroll
        for (int nt = 0; nt < 8; nt++)
#pragma unroll
            for (int j = 0; j < 4; j++) acc[mt][nt][j] = 0.f;

    const int niter = KH_ / SBK;       // 108

    stage(0, 0);
    cp_commit();

    int buf = 0;
    for (int i = 0; i < niter; i++) {
        cp_wait0();
        __syncthreads();
        if (i + 1 < niter) { stage(i + 1, buf ^ 1); cp_commit(); }

        const uint32_t* Ab =
            reinterpret_cast<const uint32_t*>(As + buf * SM_ROWS * SPA);
        const uint32_t* Bb =
            reinterpret_cast<const uint32_t*>(Bs + buf * SBK * SPB);
#pragma unroll
        for (int ks = 0; ks < SBK; ks += 8) {
            uint32_t bfr[8][2];
#pragma unroll
            for (int nt = 0; nt < 8; nt++) {
                int n = wn * 64 + nt * 8 + g;
                bfr[nt][0] = Bb[(ks + tg)     * SPB + n];
                bfr[nt][1] = Bb[(ks + tg + 4) * SPB + n];
            }
#pragma unroll
            for (int mt = 0; mt < 4; mt++) {
                int m = wm * 64 + mt * 16 + g;
                uint32_t af[4];
                af[0] = Ab[m       * SPA + ks + tg];
                af[1] = Ab[(m + 8) * SPA + ks + tg];
                af[2] = Ab[m       * SPA + ks + tg + 4];
                af[3] = Ab[(m + 8) * SPA + ks + tg + 4];
#pragma unroll
                for (int nt = 0; nt < 8; nt++)
                    mma_tf32(acc[mt][nt], af, bfr[nt]);
            }
        }
        buf ^= 1;
    }

    // ---- epilogue ----
#pragma unroll
    for (int mt = 0; mt < 4; mt++) {
#pragma unroll
        for (int half = 0; half < 2; half++) {
            int row = m0 + wm * 64 + mt * 16 + g + half * 8;
            if (row >= N_) continue;
#pragma unroll
            for (int nt = 0; nt < 8; nt++) {
                int col = wn * 64 + nt * 8 + tg * 2;
                float v0 = acc[mt][nt][half * 2 + 0] + bias[col];
                float v1 = acc[mt][nt][half * 2 + 1] + bias[col + 1];
                float o0, o1;
                if (EPI == EPI_RELU) {
                    o0 = fmaxf(v0, 0.f);
                    o1 = fmaxf(v1, 0.f);
                } else {  // EPI_R2
                    float2 a = *reinterpret_cast<const float2*>(
                        aux + (size_t)row * H_ + col);
                    o0 = fmaxf(v0, 0.f) + 2.f * a.x;
                    o1 = fmaxf(v1, 0.f) + 2.f * a.y;
                }
                if (RND) { o0 = rnd_tf32(o0); o1 = rnd_tf32(o1); }
                *reinterpret_cast<float2*>(C + (size_t)row * H_ + col) =
                    make_float2(o0, o1);
            }
        }
    }
}

// ---------------- legacy tf32 HMMA GEMM (dense / concat paths) ---------------
enum { AM_DENSE = 0, AM_CONCAT = 2 };
enum { EP_SPLIT = 0, EP_GLO = 3, EP_FINAL = 4 };

constexpr int TILE = 128;
constexpr int BK   = 32;
constexpr int PA   = BK + 4;
constexpr int PB   = TILE + 8;
constexpr int SMEM_BYTES = 2 * TILE * PA * 4 + 2 * BK * PB * 4;

template <int AMODE, int EPI, int RND>
__global__ void __launch_bounds__(256, 2)
gemm_kernel(const float* __restrict__ A, const float* __restrict__ A2,
            const float* __restrict__ Bm, int ldb, int Kdim, int lda,
            const float* __restrict__ bias,
            const float* __restrict__ aux,
            float* __restrict__ C, float* __restrict__ C2)
{
    extern __shared__ char smem_raw[];
    float* As = reinterpret_cast<float*>(smem_raw);          // [2][128][PA]
    float* Bs = As + 2 * TILE * PA;                          // [2][32][PB]

    const int tid = threadIdx.x;
    const int m0  = blockIdx.x * TILE;
    const int n0  = blockIdx.y * TILE;

    const int lane = tid & 31;
    const int wid  = tid >> 5;
    const int wm   = wid & 3;
    const int wn   = wid >> 2;
    const int g    = lane >> 2;
    const int tg   = lane & 3;

    auto stage = [&](int k0, int buf) {
        float* Ab = As + buf * TILE * PA;
        float* Bb = Bs + buf * BK * PB;
#pragma unroll
        for (int it = 0; it < 4; it++) {
            int idx = tid + it * 256;
            int r   = idx >> 3;
            int c4  = (idx & 7) << 2;
            uint32_t dst = (uint32_t)__cvta_generic_to_shared(&Ab[r * PA + c4]);
            if (AMODE == AM_DENSE) {
                int row = m0 + r;
                cp16(dst, A + (size_t)row * lda + k0 + c4, row < N_);
            } else {  // AM_CONCAT
                int row = m0 + r;
                int gc  = k0 + c4;
                const float* srcp = (gc < H_) ? A : A2;
                int cc = (gc < H_) ? gc : gc - H_;
                cp16(dst, srcp + (size_t)row * H_ + cc, row < N_);
            }
        }
#pragma unroll
        for (int it = 0; it < 4; it++) {
            int idx = tid + it * 256;
            int r   = idx >> 5;
            int c4  = (idx & 31) << 2;
            uint32_t dst = (uint32_t)__cvta_generic_to_shared(&Bb[r * PB + c4]);
            cp16(dst, Bm + (size_t)(k0 + r) * ldb + n0 + c4, true);
        }
    };

    float acc[2][8][4];
#pragma unroll
    for (int mt = 0; mt < 2; mt++)
#pragma unroll
        for (int nt = 0; nt < 8; nt++)
#pragma unroll
            for (int j = 0; j < 4; j++) acc[mt][nt][j] = 0.f;

    const int niter = Kdim / BK;
    stage(0, 0);
    cp_commit();

    int buf = 0;
    for (int i = 0; i < niter; i++) {
        cp_wait0();
        __syncthreads();
        if (i + 1 < niter) { stage((i + 1) * BK, buf ^ 1); cp_commit(); }

        const uint32_t* Ab =
            reinterpret_cast<const uint32_t*>(As + buf * TILE * PA);
        const uint32_t* Bb =
            reinterpret_cast<const uint32_t*>(Bs + buf * BK * PB);
#pragma unroll
        for (int ks = 0; ks < BK; ks += 8) {
            uint32_t bfr[8][2];
#pragma unroll
            for (int nt = 0; nt < 8; nt++) {
                int n = wn * 64 + nt * 8 + g;
                bfr[nt][0] = Bb[(ks + tg)     * PB + n];
                bfr[nt][1] = Bb[(ks + tg + 4) * PB + n];
            }
#pragma unroll
            for (int mt = 0; mt < 2; mt++) {
                int m = wm * 32 + mt * 16 + g;
                uint32_t af[4];
                af[0] = Ab[m       * PA + ks + tg];
                af[1] = Ab[(m + 8) * PA + ks + tg];
                af[2] = Ab[m       * PA + ks + tg + 4];
                af[3] = Ab[(m + 8) * PA + ks + tg + 4];
#pragma unroll
                for (int nt = 0; nt < 8; nt++)
                    mma_tf32(acc[mt][nt], af, bfr[nt]);
            }
        }
        buf ^= 1;
    }

#pragma unroll
    for (int mt = 0; mt < 2; mt++) {
#pragma unroll
        for (int half = 0; half < 2; half++) {
            int row = m0 + wm * 32 + mt * 16 + g + half * 8;
            if (row >= N_) continue;
#pragma unroll
            for (int nt = 0; nt < 8; nt++) {
                int col = n0 + wn * 64 + nt * 8 + tg * 2;
                float v0 = acc[mt][nt][half * 2 + 0] + bias[col];
                float v1 = acc[mt][nt][half * 2 + 1] + bias[col + 1];
                if (EPI == EP_SPLIT) {
                    float o0 = RND ? rnd_tf32(v0) : v0;
                    float o1 = RND ? rnd_tf32(v1) : v1;
                    if (col < H_) {
                        C [(size_t)row * H_ + col]     = o0;
                        C [(size_t)row * H_ + col + 1] = o1;
                    } else {
                        C2[(size_t)row * H_ + col - H_]     = o0;
                        C2[(size_t)row * H_ + col - H_ + 1] = o1;
                    }
                } else if (EPI == EP_GLO) {
                    float2 a = *reinterpret_cast<const float2*>(
                        aux + (size_t)row * H_ + col);
                    float o0 = fmaxf(a.x - fmaxf(v0, 0.f), 0.f);
                    float o1 = fmaxf(a.y - fmaxf(v1, 0.f), 0.f);
                    if (RND) { o0 = rnd_tf32(o0); o1 = rnd_tf32(o1); }
                    *reinterpret_cast<float2*>(C + (size_t)row * H_ + col) =
                        make_float2(o0, o1);
                } else {  // EP_FINAL
                    float2 a = *reinterpret_cast<const float2*>(
                        aux + (size_t)row * DIM_ + col);
                    *reinterpret_cast<float2*>(C + (size_t)row * DIM_ + col) =
                        make_float2(a.x + v0, a.y + v1);
                }
            }
        }
    }
}

// ---------------- deterministic segment mean (m2) ---------------------------
__global__ void seg_partial_kernel(const int* __restrict__ bids) {
    int blk = blockIdx.x;
    int o   = threadIdx.x;
    int r0  = blk * CHUNK;
    int r1  = min(r0 + CHUNK, N_);
    float a0 = 0.f, a1 = 0.f, a2 = 0.f, a3 = 0.f;
    for (int r = r0; r < r1; r++) {
        int   b = bids[r];
        float v = g_f2[(size_t)r * H_ + o];
        a0 += (b == 0) ? v : 0.f;
        a1 += (b == 1) ? v : 0.f;
        a2 += (b == 2) ? v : 0.f;
        a3 += (b == 3) ? v : 0.f;
    }
    g_part[(blk * B_ + 0) * H_ + o] = a0;
    g_part[(blk * B_ + 1) * H_ + o] = a1;
    g_part[(blk * B_ + 2) * H_ + o] = a2;
    g_part[(blk * B_ + 3) * H_ + o] = a3;
    if (o < B_) {
        int c = 0;
        for (int r = r0; r < r1; r++) c += (bids[r] == o);
        g_cnt[blk * B_ + o] = c;
    }
}

__global__ void seg_final_kernel() {
    int t = threadIdx.x;
    float s = 0.f;
    for (int p = 0; p < NPART; p++) s += g_part[p * B_ * H_ + t];
    __shared__ int scnt[B_];
    if (t < B_) {
        int c = 0;
        for (int p = 0; p < NPART; p++) c += g_cnt[p * B_ + t];
        scnt[t] = c;
    }
    __syncthreads();
    int b = t / H_;
    float cnt = (float)max(scnt[b], 1);
    g_m2[t] = s / cnt;
}

// ---------------- enc / t = enc + f1 + f2 (stores tf32-rounded) -------------
__global__ void enc_kernel(const int* __restrict__ bids) {
    int warp = threadIdx.x >> 5;
    int lane = threadIdx.x & 31;
    int row  = blockIdx.x * 4 + warp;

    float4 f1v = reinterpret_cast<const float4*>(g_f1 + (size_t)row * H_)[lane];
    float s = f1v.x + f1v.y + f1v.z + f1v.w;
#pragma unroll
    for (int off = 16; off; off >>= 1) s += __shfl_xor_sync(0xffffffffu, s, off);
    float row1 = s * (1.f / 128.f);

    int b = bids[row];
    float4 f2v = reinterpret_cast<const float4*>(g_f2 + (size_t)row * H_)[lane];
    float4 m2v = reinterpret_cast<const float4*>(g_m2 + b * H_)[lane];

    float4 t;
    t.x = rnd_tf32(sqrtf(row1 * m2v.x + 1e-12f) + f1v.x + f2v.x);
    t.y = rnd_tf32(sqrtf(row1 * m2v.y + 1e-12f) + f1v.y + f2v.y);
    t.z = rnd_tf32(sqrtf(row1 * m2v.z + 1e-12f) + f1v.z + f2v.z);
    t.w = rnd_tf32(sqrtf(row1 * m2v.w + 1e-12f) + f1v.w + f2v.w);
    reinterpret_cast<float4*>(g_t + (size_t)row * H_)[lane] = t;
}

// ---------------- launch ----------------------------------------------------
static inline void round_copy(const float* src, float* dst, int n) {
    int n4 = n / 4;
    round_copy_kernel<<<(n4 + 255) / 256, 256>>>(src, dst, n4);
}

extern "C" void kernel_launch(void* const* d_in, const int* in_sizes, int n_in,
                              void* d_out, int out_size)
{
    const float* x    = (const float*)d_in[0];
    const int*   nbr  = (const int*)  d_in[1];
    const int*   bids = (const int*)  d_in[2];
    const float* W1   = (const float*)d_in[3];
    const float* b1   = (const float*)d_in[4];
    const float* W2   = (const float*)d_in[5];
    const float* b2   = (const float*)d_in[6];
    const float* Wr1  = (const float*)d_in[7];
    const float* br1  = (const float*)d_in[8];
    const float* Wr2  = (const float*)d_in[9];
    const float* br2  = (const float*)d_in[10];
    const float* Wg1  = (const float*)d_in[11];
    const float* bg1  = (const float*)d_in[12];
    const float* Wg2  = (const float*)d_in[13];
    const float* bg2  = (const float*)d_in[14];
    const float* Wg3  = (const float*)d_in[15];
    const float* bg3  = (const float*)d_in[16];
    float* out = (float*)d_out;

    float *convx, *glo, *r1, *convout, *f1, *f2, *tb;
    float *xr, *W1r, *W2r, *Wg3r, *Wr1r, *Wr2r, *Wg1r, *Wg2r;
    cudaGetSymbolAddress((void**)&convx,   g_convx);
    cudaGetSymbolAddress((void**)&glo,     g_glo);
    cudaGetSymbolAddress((void**)&r1,      g_r1);
    cudaGetSymbolAddress((void**)&convout, g_convout);
    cudaGetSymbolAddress((void**)&f1,      g_f1);
    cudaGetSymbolAddress((void**)&f2,      g_f2);
    cudaGetSymbolAddress((void**)&tb,      g_t);
    cudaGetSymbolAddress((void**)&xr,      g_xr);
    cudaGetSymbolAddress((void**)&W1r,     g_W1r);
    cudaGetSymbolAddress((void**)&W2r,     g_W2r);
    cudaGetSymbolAddress((void**)&Wg3r,    g_Wg3r);
    cudaGetSymbolAddress((void**)&Wr1r,    g_Wr1r);
    cudaGetSymbolAddress((void**)&Wr2r,    g_Wr2r);
    cudaGetSymbolAddress((void**)&Wg1r,    g_Wg1r);
    cudaGetSymbolAddress((void**)&Wg2r,    g_Wg2r);

    cudaFuncSetAttribute(gemm_kernel<AM_DENSE,  EP_SPLIT, 1>,
                         cudaFuncAttributeMaxDynamicSharedMemorySize, SMEM_BYTES);
    cudaFuncSetAttribute(gemm_kernel<AM_DENSE,  EP_GLO,   1>,
                         cudaFuncAttributeMaxDynamicSharedMemorySize, SMEM_BYTES);
    cudaFuncSetAttribute(gemm_kernel<AM_CONCAT, EP_FINAL, 0>,
                         cudaFuncAttributeMaxDynamicSharedMemorySize, SMEM_BYTES);
    cudaFuncSetAttribute(sconv_big_kernel<EPI_RELU, 1>,
                         cudaFuncAttributeMaxDynamicSharedMemorySize, SCONV_SMEM);
    cudaFuncSetAttribute(sconv_big_kernel<EPI_RELU, 0>,
                         cudaFuncAttributeMaxDynamicSharedMemorySize, SCONV_SMEM);
    cudaFuncSetAttribute(sconv_big_kernel<EPI_R2,   1>,
                         cudaFuncAttributeMaxDynamicSharedMemorySize, SCONV_SMEM);

    const int mt  = (N_ + TILE - 1) / TILE;        // 313
    const int mt2 = (N_ + SM_ROWS - 1) / SM_ROWS;  // 157
    dim3 blk(256);

    // ---- prep: tf32-round all static GEMM operands ----
    round_copy(x,   xr,   N_ * DIM_);
    round_copy(W1,  W1r,  DIM_ * DIM_);
    round_copy(W2,  W2r,  DIM_ * DIM_);
    round_copy(Wg3, Wg3r, H_ * H_);
    round_copy(Wr1, Wr1r, KH_ * H_);
    round_copy(Wr2, Wr2r, KH_ * H_);
    round_copy(Wg1, Wg1r, KH_ * H_);
    round_copy(Wg2, Wg2r, KH_ * H_);
    zero_pad_kernel<<<1, 128>>>();

    // h = x@W1 + b1 ; conv_x = h[:, :128] ; glo = h[:, 128:]  (stored rounded)
    gemm_kernel<AM_DENSE, EP_SPLIT, 1><<<dim3(mt, 2), blk, SMEM_BYTES>>>(
        xr, nullptr, W1r, DIM_, DIM_, DIM_, b1, nullptr, convx, glo);

    // sconvs: big-tile HMMA kernels
    sconv_big_kernel<EPI_RELU, 1><<<mt2, blk, SCONV_SMEM>>>(
        convx, nbr, Wr1r, br1, nullptr, r1);
    sconv_big_kernel<EPI_R2, 1><<<mt2, blk, SCONV_SMEM>>>(
        r1, nbr, Wr2r, br2, convx, convout);
    sconv_big_kernel<EPI_RELU, 0><<<mt2, blk, SCONV_SMEM>>>(
        glo, nbr, Wg1r, bg1, nullptr, f1);
    sconv_big_kernel<EPI_RELU, 0><<<mt2, blk, SCONV_SMEM>>>(
        glo, nbr, Wg2r, bg2, nullptr, f2);

    // m2 = segment_mean(f2) (deterministic two-pass)
    seg_partial_kernel<<<NPART, 128>>>(bids);
    seg_final_kernel<<<1, 512>>>();

    // t = sqrt(mean(f1)*m2[bid] + 1e-12) + f1 + f2   (stored rounded)
    enc_kernel<<<N_ / 4, 128>>>(bids);

    // glo = relu(glo - relu(t@Wg3 + bg3))   (stored rounded)
    gemm_kernel<AM_DENSE, EP_GLO, 1><<<dim3(mt, 1), blk, SMEM_BYTES>>>(
        tb, nullptr, Wg3r, H_, H_, H_, bg3, glo, glo, nullptr);

    // out = x + [convout | glo] @ W2 + b2
    gemm_kernel<AM_CONCAT, EP_FINAL, 0><<<dim3(mt, 2), blk, SMEM_BYTES>>>(
        convout, glo, W2r, DIM_, DIM_, 0, b2, x, out, nullptr);
}

// round 11
// speedup vs baseline: 1.2500x; 1.2500x over previous
#include <cuda_runtime.h>
#include <math.h>
#include <stdint.h>

// Problem constants (fixed shapes for GCM_60490319396973)
constexpr int N_   = 40000;
constexpr int DIM_ = 256;
constexpr int H_   = 128;
constexpr int K_   = 27;
constexpr int B_   = 4;
constexpr int KH_  = K_ * H_;      // 3456
constexpr int NPART = 250;
constexpr int CHUNK = (N_ + NPART - 1) / NPART;   // 160

// ---------------- scratch (device globals: no allocation allowed) ----------
__device__ float g_convx[(N_ + 1) * H_];   // padded: row N_ is the zero row
__device__ float g_glo  [(N_ + 1) * H_];
__device__ float g_r1   [(N_ + 1) * H_];
__device__ float g_convout[N_ * H_];
__device__ float g_f1[N_ * H_];
__device__ float g_f2[N_ * H_];
__device__ float g_t [N_ * H_];
__device__ float g_part[NPART * B_ * H_];
__device__ int   g_cnt [NPART * B_];
__device__ float g_m2  [B_ * H_];
// tf32-pre-rounded operands
__device__ float g_xr  [N_ * DIM_];
__device__ float g_W1r [DIM_ * DIM_];
__device__ float g_W2r [DIM_ * DIM_];
__device__ float g_Wg3r[H_ * H_];
__device__ float g_Wr1r[KH_ * H_];
__device__ float g_Wr2r[KH_ * H_];
__device__ float g_Wg1r[KH_ * H_];
__device__ float g_Wg2r[KH_ * H_];

// ---------------- helpers ----------------------------------------------------
__device__ __forceinline__ uint32_t f2tf32(float x) {
    uint32_t y;
    asm("cvt.rna.tf32.f32 %0, %1;" : "=r"(y) : "f"(x));
    return y;
}
__device__ __forceinline__ float rnd_tf32(float x) {
    return __uint_as_float(f2tf32(x));
}
__device__ __forceinline__ void mma_tf32(float c[4], const uint32_t a[4],
                                         const uint32_t b[2]) {
    asm volatile(
        "mma.sync.aligned.m16n8k8.row.col.f32.tf32.tf32.f32 "
        "{%0,%1,%2,%3}, {%4,%5,%6,%7}, {%8,%9}, {%0,%1,%2,%3};\n"
        : "+f"(c[0]), "+f"(c[1]), "+f"(c[2]), "+f"(c[3])
        : "r"(a[0]), "r"(a[1]), "r"(a[2]), "r"(a[3]), "r"(b[0]), "r"(b[1]));
}
__device__ __forceinline__ void cp16(uint32_t dst, const void* src, bool valid) {
    asm volatile("cp.async.cg.shared.global [%0], [%1], 16, %2;"
                 :: "r"(dst), "l"(src), "r"(valid ? 16 : 0));
}
__device__ __forceinline__ void cp16g(uint32_t dst, const void* src) {
    asm volatile("cp.async.cg.shared.global [%0], [%1], 16;"
                 :: "r"(dst), "l"(src));
}
__device__ __forceinline__ void cp_commit() {
    asm volatile("cp.async.commit_group;");
}
template <int NN>
__device__ __forceinline__ void cp_wait_n() {
    asm volatile("cp.async.wait_group %0;" :: "n"(NN));
}

// ---------------- tiny kernels ---------------------------------------------
__global__ void zero_pad_kernel() {
    int t = threadIdx.x;                 // 128 threads
    g_convx[N_ * H_ + t] = 0.f;
    g_glo  [N_ * H_ + t] = 0.f;
    g_r1   [N_ * H_ + t] = 0.f;
}

__global__ void round_copy_kernel(const float* __restrict__ src,
                                  float* __restrict__ dst, int n4) {
    int i = blockIdx.x * blockDim.x + threadIdx.x;
    if (i >= n4) return;
    float4 v = reinterpret_cast<const float4*>(src)[i];
    v.x = rnd_tf32(v.x); v.y = rnd_tf32(v.y);
    v.z = rnd_tf32(v.z); v.w = rnd_tf32(v.w);
    reinterpret_cast<float4*>(dst)[i] = v;
}

// ---------------- sconv: tf32 HMMA, 128x128 tile, 3-stage cp.async ----------
// C[m, 0:128] = epi( bias + sum_{k,c} A[nbr[m,k], c] * W[k*128+c, :] )
enum { EPI_RELU = 0, EPI_R2 = 1 };

constexpr int STILE = 128;
constexpr int SBK   = 32;
constexpr int SPA   = SBK + 4;         // 36
constexpr int SPB   = STILE + 8;       // 136
constexpr int SNBUF = 3;
constexpr int SNT   = KH_ / SBK;       // 108
constexpr int SCONV_SMEM = SNBUF * (STILE * SPA + SBK * SPB) * 4;  // 107520

template <int EPI, int RND>
__global__ void __launch_bounds__(256, 2)
sconv_kernel(const float* __restrict__ A,   // (N_+1) x 128, rounded, zero row N_
             const int* __restrict__ nbr,
             const float* __restrict__ Bm,  // [3456][128], rounded
             const float* __restrict__ bias,
             const float* __restrict__ aux,
             float* __restrict__ C)
{
    extern __shared__ char smem_raw[];
    float* As = reinterpret_cast<float*>(smem_raw);      // [3][128][SPA]
    float* Bs = As + SNBUF * STILE * SPA;                // [3][32][SPB]

    const int tid  = threadIdx.x;
    const int m0   = blockIdx.x * STILE;
    const int lane = tid & 31;
    const int wid  = tid >> 5;         // 0..7
    const int wm   = wid & 3;          // warp row (4 x 32 = 128)
    const int wn   = wid >> 2;         // warp col (2 x 64 = 128)
    const int g    = lane >> 2;        // 0..7
    const int tg   = lane & 3;         // 0..3

    // each thread stages rows rb, rb+32, rb+64, rb+96 every tile
    const int rb = tid >> 3;           // 0..31
    const int c4 = (tid & 7) << 2;     // 0..28

    int nv[4];
    auto load_nidx = [&](int kidx) {
#pragma unroll
        for (int j = 0; j < 4; j++) {
            int row = m0 + rb + 32 * j;
            nv[j] = (row < N_) ? nbr[row * K_ + kidx] : N_;   // N_ -> zero row
        }
    };

    auto stage = [&](int s) {
        int b = s % SNBUF;
        int csub = (s & 3) * SBK;          // feature offset within node row
        int k0 = s * SBK;
        float* Ab = As + b * STILE * SPA;
        float* Bb = Bs + b * SBK * SPB;
        // A: 128 rows x 32 cols (each thread: its 4 rows, one 16B chunk each)
#pragma unroll
        for (int j = 0; j < 4; j++) {
            int r = rb + 32 * j;
            uint32_t dst = (uint32_t)__cvta_generic_to_shared(&Ab[r * SPA + c4]);
            cp16g(dst, A + (size_t)nv[j] * H_ + csub + c4);
        }
        // B: 32 rows x 128 cols = 1024 float4
#pragma unroll
        for (int it = 0; it < 4; it++) {
            int idx = tid + it * 256;
            int r   = idx >> 5;            // 0..31
            int cc  = (idx & 31) << 2;     // 0..124
            uint32_t dst = (uint32_t)__cvta_generic_to_shared(&Bb[r * SPB + cc]);
            cp16g(dst, Bm + (size_t)(k0 + r) * H_ + cc);
        }
    };

    float acc[2][8][4];
#pragma unroll
    for (int mt = 0; mt < 2; mt++)
#pragma unroll
        for (int nt = 0; nt < 8; nt++)
#pragma unroll
            for (int j = 0; j < 4; j++) acc[mt][nt][j] = 0.f;

    load_nidx(0);
    stage(0); cp_commit();
    stage(1); cp_commit();          // tiles 0,1 are both k-slot 0

    for (int t = 0; t < SNT; t++) {
        if (t < SNT - 1) cp_wait_n<1>(); else cp_wait_n<0>();
        __syncthreads();

        int s = t + 2;
        if (s < SNT) {
            if ((s & 3) == 0) load_nidx(s >> 2);
            stage(s); cp_commit();
        }

        const uint32_t* Ab =
            reinterpret_cast<const uint32_t*>(As + (t % SNBUF) * STILE * SPA);
        const uint32_t* Bb =
            reinterpret_cast<const uint32_t*>(Bs + (t % SNBUF) * SBK * SPB);
#pragma unroll
        for (int ks = 0; ks < SBK; ks += 8) {
            uint32_t bfr[8][2];
#pragma unroll
            for (int nt = 0; nt < 8; nt++) {
                int n = wn * 64 + nt * 8 + g;
                bfr[nt][0] = Bb[(ks + tg)     * SPB + n];
                bfr[nt][1] = Bb[(ks + tg + 4) * SPB + n];
            }
#pragma unroll
            for (int mt = 0; mt < 2; mt++) {
                int m = wm * 32 + mt * 16 + g;
                uint32_t af[4];
                af[0] = Ab[m       * SPA + ks + tg];
                af[1] = Ab[(m + 8) * SPA + ks + tg];
                af[2] = Ab[m       * SPA + ks + tg + 4];
                af[3] = Ab[(m + 8) * SPA + ks + tg + 4];
#pragma unroll
                for (int nt = 0; nt < 8; nt++)
                    mma_tf32(acc[mt][nt], af, bfr[nt]);
            }
        }
    }

    // ---- epilogue ----
#pragma unroll
    for (int mt = 0; mt < 2; mt++) {
#pragma unroll
        for (int half = 0; half < 2; half++) {
            int row = m0 + wm * 32 + mt * 16 + g + half * 8;
            if (row >= N_) continue;
#pragma unroll
            for (int nt = 0; nt < 8; nt++) {
                int col = wn * 64 + nt * 8 + tg * 2;
                float v0 = acc[mt][nt][half * 2 + 0] + bias[col];
                float v1 = acc[mt][nt][half * 2 + 1] + bias[col + 1];
                float o0, o1;
                if (EPI == EPI_RELU) {
                    o0 = fmaxf(v0, 0.f);
                    o1 = fmaxf(v1, 0.f);
                } else {  // EPI_R2
                    float2 a = *reinterpret_cast<const float2*>(
                        aux + (size_t)row * H_ + col);
                    o0 = fmaxf(v0, 0.f) + 2.f * a.x;
                    o1 = fmaxf(v1, 0.f) + 2.f * a.y;
                }
                if (RND) { o0 = rnd_tf32(o0); o1 = rnd_tf32(o1); }
                *reinterpret_cast<float2*>(C + (size_t)row * H_ + col) =
                    make_float2(o0, o1);
            }
        }
    }
}

// ---------------- legacy tf32 HMMA GEMM (dense / concat paths) ---------------
enum { AM_DENSE = 0, AM_CONCAT = 2 };
enum { EP_SPLIT = 0, EP_GLO = 3, EP_FINAL = 4 };

constexpr int TILE = 128;
constexpr int BK   = 32;
constexpr int PA   = BK + 4;
constexpr int PB   = TILE + 8;
constexpr int SMEM_BYTES = 2 * TILE * PA * 4 + 2 * BK * PB * 4;

template <int AMODE, int EPI, int RND>
__global__ void __launch_bounds__(256, 2)
gemm_kernel(const float* __restrict__ A, const float* __restrict__ A2,
            const float* __restrict__ Bm, int ldb, int Kdim, int lda,
            const float* __restrict__ bias,
            const float* __restrict__ aux,
            float* __restrict__ C, float* __restrict__ C2)
{
    extern __shared__ char smem_raw[];
    float* As = reinterpret_cast<float*>(smem_raw);          // [2][128][PA]
    float* Bs = As + 2 * TILE * PA;                          // [2][32][PB]

    const int tid = threadIdx.x;
    const int m0  = blockIdx.x * TILE;
    const int n0  = blockIdx.y * TILE;

    const int lane = tid & 31;
    const int wid  = tid >> 5;
    const int wm   = wid & 3;
    const int wn   = wid >> 2;
    const int g    = lane >> 2;
    const int tg   = lane & 3;

    auto stage = [&](int k0, int buf) {
        float* Ab = As + buf * TILE * PA;
        float* Bb = Bs + buf * BK * PB;
#pragma unroll
        for (int it = 0; it < 4; it++) {
            int idx = tid + it * 256;
            int r   = idx >> 3;
            int c4  = (idx & 7) << 2;
            uint32_t dst = (uint32_t)__cvta_generic_to_shared(&Ab[r * PA + c4]);
            if (AMODE == AM_DENSE) {
                int row = m0 + r;
                cp16(dst, A + (size_t)row * lda + k0 + c4, row < N_);
            } else {  // AM_CONCAT
                int row = m0 + r;
                int gc  = k0 + c4;
                const float* srcp = (gc < H_) ? A : A2;
                int cc = (gc < H_) ? gc : gc - H_;
                cp16(dst, srcp + (size_t)row * H_ + cc, row < N_);
            }
        }
#pragma unroll
        for (int it = 0; it < 4; it++) {
            int idx = tid + it * 256;
            int r   = idx >> 5;
            int c4  = (idx & 31) << 2;
            uint32_t dst = (uint32_t)__cvta_generic_to_shared(&Bb[r * PB + c4]);
            cp16(dst, Bm + (size_t)(k0 + r) * ldb + n0 + c4, true);
        }
    };

    float acc[2][8][4];
#pragma unroll
    for (int mt = 0; mt < 2; mt++)
#pragma unroll
        for (int nt = 0; nt < 8; nt++)
#pragma unroll
            for (int j = 0; j < 4; j++) acc[mt][nt][j] = 0.f;

    const int niter = Kdim / BK;
    stage(0, 0);
    cp_commit();

    int buf = 0;
    for (int i = 0; i < niter; i++) {
        cp_wait_n<0>();
        __syncthreads();
        if (i + 1 < niter) { stage((i + 1) * BK, buf ^ 1); cp_commit(); }

        const uint32_t* Ab =
            reinterpret_cast<const uint32_t*>(As + buf * TILE * PA);
        const uint32_t* Bb =
            reinterpret_cast<const uint32_t*>(Bs + buf * BK * PB);
#pragma unroll
        for (int ks = 0; ks < BK; ks += 8) {
            uint32_t bfr[8][2];
#pragma unroll
            for (int nt = 0; nt < 8; nt++) {
                int n = wn * 64 + nt * 8 + g;
                bfr[nt][0] = Bb[(ks + tg)     * PB + n];
                bfr[nt][1] = Bb[(ks + tg + 4) * PB + n];
            }
#pragma unroll
            for (int mt = 0; mt < 2; mt++) {
                int m = wm * 32 + mt * 16 + g;
                uint32_t af[4];
                af[0] = Ab[m       * PA + ks + tg];
                af[1] = Ab[(m + 8) * PA + ks + tg];
                af[2] = Ab[m       * PA + ks + tg + 4];
                af[3] = Ab[(m + 8) * PA + ks + tg + 4];
#pragma unroll
                for (int nt = 0; nt < 8; nt++)
                    mma_tf32(acc[mt][nt], af, bfr[nt]);
            }
        }
        buf ^= 1;
    }

#pragma unroll
    for (int mt = 0; mt < 2; mt++) {
#pragma unroll
        for (int half = 0; half < 2; half++) {
            int row = m0 + wm * 32 + mt * 16 + g + half * 8;
            if (row >= N_) continue;
#pragma unroll
            for (int nt = 0; nt < 8; nt++) {
                int col = n0 + wn * 64 + nt * 8 + tg * 2;
                float v0 = acc[mt][nt][half * 2 + 0] + bias[col];
                float v1 = acc[mt][nt][half * 2 + 1] + bias[col + 1];
                if (EPI == EP_SPLIT) {
                    float o0 = RND ? rnd_tf32(v0) : v0;
                    float o1 = RND ? rnd_tf32(v1) : v1;
                    if (col < H_) {
                        C [(size_t)row * H_ + col]     = o0;
                        C [(size_t)row * H_ + col + 1] = o1;
                    } else {
                        C2[(size_t)row * H_ + col - H_]     = o0;
                        C2[(size_t)row * H_ + col - H_ + 1] = o1;
                    }
                } else if (EPI == EP_GLO) {
                    float2 a = *reinterpret_cast<const float2*>(
                        aux + (size_t)row * H_ + col);
                    float o0 = fmaxf(a.x - fmaxf(v0, 0.f), 0.f);
                    float o1 = fmaxf(a.y - fmaxf(v1, 0.f), 0.f);
                    if (RND) { o0 = rnd_tf32(o0); o1 = rnd_tf32(o1); }
                    *reinterpret_cast<float2*>(C + (size_t)row * H_ + col) =
                        make_float2(o0, o1);
                } else {  // EP_FINAL
                    float2 a = *reinterpret_cast<const float2*>(
                        aux + (size_t)row * DIM_ + col);
                    *reinterpret_cast<float2*>(C + (size_t)row * DIM_ + col) =
                        make_float2(a.x + v0, a.y + v1);
                }
            }
        }
    }
}

// ---------------- deterministic segment mean (m2) ---------------------------
__global__ void seg_partial_kernel(const int* __restrict__ bids) {
    int blk = blockIdx.x;
    int o   = threadIdx.x;
    int r0  = blk * CHUNK;
    int r1  = min(r0 + CHUNK, N_);
    float a0 = 0.f, a1 = 0.f, a2 = 0.f, a3 = 0.f;
    for (int r = r0; r < r1; r++) {
        int   b = bids[r];
        float v = g_f2[(size_t)r * H_ + o];
        a0 += (b == 0) ? v : 0.f;
        a1 += (b == 1) ? v : 0.f;
        a2 += (b == 2) ? v : 0.f;
        a3 += (b == 3) ? v : 0.f;
    }
    g_part[(blk * B_ + 0) * H_ + o] = a0;
    g_part[(blk * B_ + 1) * H_ + o] = a1;
    g_part[(blk * B_ + 2) * H_ + o] = a2;
    g_part[(blk * B_ + 3) * H_ + o] = a3;
    if (o < B_) {
        int c = 0;
        for (int r = r0; r < r1; r++) c += (bids[r] == o);
        g_cnt[blk * B_ + o] = c;
    }
}

__global__ void seg_final_kernel() {
    int t = threadIdx.x;
    float s = 0.f;
    for (int p = 0; p < NPART; p++) s += g_part[p * B_ * H_ + t];
    __shared__ int scnt[B_];
    if (t < B_) {
        int c = 0;
        for (int p = 0; p < NPART; p++) c += g_cnt[p * B_ + t];
        scnt[t] = c;
    }
    __syncthreads();
    int b = t / H_;
    float cnt = (float)max(scnt[b], 1);
    g_m2[t] = s / cnt;
}

// ---------------- enc / t = enc + f1 + f2 (stores tf32-rounded) -------------
__global__ void enc_kernel(const int* __restrict__ bids) {
    int warp = threadIdx.x >> 5;
    int lane = threadIdx.x & 31;
    int row  = blockIdx.x * 4 + warp;

    float4 f1v = reinterpret_cast<const float4*>(g_f1 + (size_t)row * H_)[lane];
    float s = f1v.x + f1v.y + f1v.z + f1v.w;
#pragma unroll
    for (int off = 16; off; off >>= 1) s += __shfl_xor_sync(0xffffffffu, s, off);
    float row1 = s * (1.f / 128.f);

    int b = bids[row];
    float4 f2v = reinterpret_cast<const float4*>(g_f2 + (size_t)row * H_)[lane];
    float4 m2v = reinterpret_cast<const float4*>(g_m2 + b * H_)[lane];

    float4 t;
    t.x = rnd_tf32(sqrtf(row1 * m2v.x + 1e-12f) + f1v.x + f2v.x);
    t.y = rnd_tf32(sqrtf(row1 * m2v.y + 1e-12f) + f1v.y + f2v.y);
    t.z = rnd_tf32(sqrtf(row1 * m2v.z + 1e-12f) + f1v.z + f2v.z);
    t.w = rnd_tf32(sqrtf(row1 * m2v.w + 1e-12f) + f1v.w + f2v.w);
    reinterpret_cast<float4*>(g_t + (size_t)row * H_)[lane] = t;
}

// ---------------- launch ----------------------------------------------------
static inline void round_copy(const float* src, float* dst, int n) {
    int n4 = n / 4;
    round_copy_kernel<<<(n4 + 255) / 256, 256>>>(src, dst, n4);
}

extern "C" void kernel_launch(void* const* d_in, const int* in_sizes, int n_in,
                              void* d_out, int out_size)
{
    const float* x    = (const float*)d_in[0];
    const int*   nbr  = (const int*)  d_in[1];
    const int*   bids = (const int*)  d_in[2];
    const float* W1   = (const float*)d_in[3];
    const float* b1   = (const float*)d_in[4];
    const float* W2   = (const float*)d_in[5];
    const float* b2   = (const float*)d_in[6];
    const float* Wr1  = (const float*)d_in[7];
    const float* br1  = (const float*)d_in[8];
    const float* Wr2  = (const float*)d_in[9];
    const float* br2  = (const float*)d_in[10];
    const float* Wg1  = (const float*)d_in[11];
    const float* bg1  = (const float*)d_in[12];
    const float* Wg2  = (const float*)d_in[13];
    const float* bg2  = (const float*)d_in[14];
    const float* Wg3  = (const float*)d_in[15];
    const float* bg3  = (const float*)d_in[16];
    float* out = (float*)d_out;

    float *convx, *glo, *r1, *convout, *f1, *f2, *tb;
    float *xr, *W1r, *W2r, *Wg3r, *Wr1r, *Wr2r, *Wg1r, *Wg2r;
    cudaGetSymbolAddress((void**)&convx,   g_convx);
    cudaGetSymbolAddress((void**)&glo,     g_glo);
    cudaGetSymbolAddress((void**)&r1,      g_r1);
    cudaGetSymbolAddress((void**)&convout, g_convout);
    cudaGetSymbolAddress((void**)&f1,      g_f1);
    cudaGetSymbolAddress((void**)&f2,      g_f2);
    cudaGetSymbolAddress((void**)&tb,      g_t);
    cudaGetSymbolAddress((void**)&xr,      g_xr);
    cudaGetSymbolAddress((void**)&W1r,     g_W1r);
    cudaGetSymbolAddress((void**)&W2r,     g_W2r);
    cudaGetSymbolAddress((void**)&Wg3r,    g_Wg3r);
    cudaGetSymbolAddress((void**)&Wr1r,    g_Wr1r);
    cudaGetSymbolAddress((void**)&Wr2r,    g_Wr2r);
    cudaGetSymbolAddress((void**)&Wg1r,    g_Wg1r);
    cudaGetSymbolAddress((void**)&Wg2r,    g_Wg2r);

    cudaFuncSetAttribute(gemm_kernel<AM_DENSE,  EP_SPLIT, 1>,
                         cudaFuncAttributeMaxDynamicSharedMemorySize, SMEM_BYTES);
    cudaFuncSetAttribute(gemm_kernel<AM_DENSE,  EP_GLO,   1>,
                         cudaFuncAttributeMaxDynamicSharedMemorySize, SMEM_BYTES);
    cudaFuncSetAttribute(gemm_kernel<AM_CONCAT, EP_FINAL, 0>,
                         cudaFuncAttributeMaxDynamicSharedMemorySize, SMEM_BYTES);
    cudaFuncSetAttribute(sconv_kernel<EPI_RELU, 1>,
                         cudaFuncAttributeMaxDynamicSharedMemorySize, SCONV_SMEM);
    cudaFuncSetAttribute(sconv_kernel<EPI_RELU, 0>,
                         cudaFuncAttributeMaxDynamicSharedMemorySize, SCONV_SMEM);
    cudaFuncSetAttribute(sconv_kernel<EPI_R2,   1>,
                         cudaFuncAttributeMaxDynamicSharedMemorySize, SCONV_SMEM);

    const int mt = (N_ + TILE - 1) / TILE;   // 313
    dim3 blk(256);

    // ---- prep: tf32-round all static GEMM operands ----
    round_copy(x,   xr,   N_ * DIM_);
    round_copy(W1,  W1r,  DIM_ * DIM_);
    round_copy(W2,  W2r,  DIM_ * DIM_);
    round_copy(Wg3, Wg3r, H_ * H_);
    round_copy(Wr1, Wr1r, KH_ * H_);
    round_copy(Wr2, Wr2r, KH_ * H_);
    round_copy(Wg1, Wg1r, KH_ * H_);
    round_copy(Wg2, Wg2r, KH_ * H_);
    zero_pad_kernel<<<1, 128>>>();

    // h = x@W1 + b1 ; conv_x = h[:, :128] ; glo = h[:, 128:]  (stored rounded)
    gemm_kernel<AM_DENSE, EP_SPLIT, 1><<<dim3(mt, 2), blk, SMEM_BYTES>>>(
        xr, nullptr, W1r, DIM_, DIM_, DIM_, b1, nullptr, convx, glo);

    // sconvs: 3-stage pipelined HMMA kernels
    sconv_kernel<EPI_RELU, 1><<<mt, blk, SCONV_SMEM>>>(
        convx, nbr, Wr1r, br1, nullptr, r1);
    sconv_kernel<EPI_R2, 1><<<mt, blk, SCONV_SMEM>>>(
        r1, nbr, Wr2r, br2, convx, convout);
    sconv_kernel<EPI_RELU, 0><<<mt, blk, SCONV_SMEM>>>(
        glo, nbr, Wg1r, bg1, nullptr, f1);
    sconv_kernel<EPI_RELU, 0><<<mt, blk, SCONV_SMEM>>>(
        glo, nbr, Wg2r, bg2, nullptr, f2);

    // m2 = segment_mean(f2) (deterministic two-pass)
    seg_partial_kernel<<<NPART, 128>>>(bids);
    seg_final_kernel<<<1, 512>>>();

    // t = sqrt(mean(f1)*m2[bid] + 1e-12) + f1 + f2   (stored rounded)
    enc_kernel<<<N_ / 4, 128>>>(bids);

    // glo = relu(glo - relu(t@Wg3 + bg3))   (stored rounded)
    gemm_kernel<AM_DENSE, EP_GLO, 1><<<dim3(mt, 1), blk, SMEM_BYTES>>>(
        tb, nullptr, Wg3r, H_, H_, H_, bg3, glo, glo, nullptr);

    // out = x + [convout | glo] @ W2 + b2
    gemm_kernel<AM_CONCAT, EP_FINAL, 0><<<dim3(mt, 2), blk, SMEM_BYTES>>>(
        convout, glo, W2r, DIM_, DIM_, 0, b2, x, out, nullptr);
}